// round 13
// baseline (speedup 1.0000x reference)
#include <cuda_runtime.h>
#include <cuda_bf16.h>

// AdaptiveURBFLayer: out[b,j] = exp(-0.5*z^2)*coef[j], z = (x[b,src[j]]-mean[j])/var[j]
// Rewritten: out = ex2( a_j * (v - m_j)^2 ) * c_j,  a_j = -0.5*log2(e)/var_j^2

namespace urbf {

constexpr int kIn    = 256;
constexpr int kOut   = 4096;
constexpr int kBatch = 8192;
constexpr int kRows  = 8;      // batch rows per CTA
constexpr int kJBlk  = 1024;   // j-span per CTA (256 threads x 4)

// Packed per-out-feature params: {mean, a(=-0.5*log2e*inv_var^2), coef, src_bits}
__device__ float4 d_params[kOut];

} // namespace urbf

__device__ __forceinline__ float ex2_approx(float v) {
    float r;
    asm("ex2.approx.ftz.f32 %0, %1;" : "=f"(r) : "f"(v));
    return r;
}

// Prologue: scan expansion_mapping as float4 (one thread per vec4 element).
__global__ void urbf_build_params(const float4* __restrict__ em4,
                                  const float* __restrict__ means,
                                  const float* __restrict__ vars_,
                                  const float* __restrict__ coefs) {
    using namespace urbf;
    const int tid = blockIdx.x * blockDim.x + threadIdx.x;   // [0, kOut*kIn/4)
    const int j = tid / (kIn / 4);
    const int i0 = (tid - j * (kIn / 4)) * 4;
    const float4 e = em4[tid];

    int hit = -1;
    if (e.x > 0.5f) hit = i0;
    if (e.y > 0.5f) hit = i0 + 1;
    if (e.z > 0.5f) hit = i0 + 2;
    if (e.w > 0.5f) hit = i0 + 3;

    if (hit >= 0) {
        const float iv = 1.0f / __ldg(vars_ + j);
        float4 p;
        p.x = __ldg(means + j);
        p.y = -0.72134752044448170f * iv * iv;   // -0.5 * log2(e) * inv_var^2
        p.z = __ldg(coefs + j);
        p.w = __int_as_float(hit);
        d_params[j] = p;
    }
}

// Main kernel. CTA = 256 threads; each thread owns 4 consecutive j and walks
// kRows consecutive batch rows. Per output: FADD, FMUL, FMUL, MUFU.EX2, FMUL.
__global__ __launch_bounds__(256) void urbf_main(const float* __restrict__ x,
                                                 float* __restrict__ out) {
    using namespace urbf;
    const int jb = blockIdx.x & 3;
    const int rb = blockIdx.x >> 2;
    const int j = jb * kJBlk + threadIdx.x * 4;

    const float4 p0 = d_params[j];
    const float4 p1 = d_params[j + 1];
    const float4 p2 = d_params[j + 2];
    const float4 p3 = d_params[j + 3];
    const int s0 = __float_as_int(p0.w);
    const int s1 = __float_as_int(p1.w);
    const int s2 = __float_as_int(p2.w);
    const int s3 = __float_as_int(p3.w);
    const bool same_src = (s0 == s1) & (s1 == s2) & (s2 == s3);

    const float* xr = x + (size_t)rb * kRows * kIn;
    float* op = out + (size_t)rb * kRows * kOut + j;

    #pragma unroll
    for (int r = 0; r < kRows; ++r, xr += kIn, op += kOut) {
        float v0, v1, v2, v3;
        if (same_src) {
            v0 = __ldg(xr + s0);
            v1 = v0; v2 = v0; v3 = v0;
        } else {
            v0 = __ldg(xr + s0);
            v1 = __ldg(xr + s1);
            v2 = __ldg(xr + s2);
            v3 = __ldg(xr + s3);
        }

        const float t0 = v0 - p0.x;
        const float t1 = v1 - p1.x;
        const float t2 = v2 - p2.x;
        const float t3 = v3 - p3.x;

        float4 o;
        o.x = ex2_approx(p0.y * (t0 * t0)) * p0.z;
        o.y = ex2_approx(p1.y * (t1 * t1)) * p1.z;
        o.z = ex2_approx(p2.y * (t2 * t2)) * p2.z;
        o.w = ex2_approx(p3.y * (t3 * t3)) * p3.z;

        *reinterpret_cast<float4*>(op) = o;
    }
}

extern "C" void kernel_launch(void* const* d_in, const int* in_sizes, int n_in,
                              void* d_out, int out_size) {
    using namespace urbf;
    const float* x     = (const float*)d_in[0];  // [8192, 256]
    const float* em    = (const float*)d_in[1];  // [4096, 256]
    const float* means = (const float*)d_in[2];  // [4096]
    const float* vars_ = (const float*)d_in[3];  // [4096]
    const float* coefs = (const float*)d_in[4];  // [4096]
    float* out = (float*)d_out;                  // [8192, 4096]

    {
        const int n4 = kOut * kIn / 4;                       // 262,144
        urbf_build_params<<<n4 / 256, 256>>>((const float4*)em, means, vars_, coefs);
    }
    {
        const int grid = (kOut / kJBlk) * (kBatch / kRows);  // 4096
        urbf_main<<<grid, 256>>>(x, out);
    }
}

// round 14
// speedup vs baseline: 1.3679x; 1.3679x over previous
#include <cuda_runtime.h>
#include <cuda_bf16.h>

// AdaptiveURBFLayer: out[b,j] = exp(-0.5*z^2)*coef[j], z = (x[b,src[j]]-mean[j])/var[j]
// Rewritten: out = ex2( a_j * (v - m_j)^2 ) * c_j,  a_j = -0.5*log2(e)/var_j^2

namespace urbf {

constexpr int kIn    = 256;
constexpr int kOut   = 4096;
constexpr int kBatch = 8192;
constexpr int kRows  = 8;      // batch rows per CTA
constexpr int kJBlk  = 1024;   // j-span per CTA (256 threads x 4)

// Packed per-out-feature params: {mean, a(=-0.5*log2e*inv_var^2), coef, src_bits}
__device__ float4 d_params[kOut];

} // namespace urbf

__device__ __forceinline__ float ex2_approx(float v) {
    float r;
    asm("ex2.approx.ftz.f32 %0, %1;" : "=f"(r) : "f"(v));
    return r;
}

// Prologue: scan expansion_mapping as float4 (one thread per vec4 element).
__global__ void urbf_build_params(const float4* __restrict__ em4,
                                  const float* __restrict__ means,
                                  const float* __restrict__ vars_,
                                  const float* __restrict__ coefs) {
    using namespace urbf;
    const int tid = blockIdx.x * blockDim.x + threadIdx.x;   // [0, kOut*kIn/4)
    const int j = tid / (kIn / 4);
    const int i0 = (tid - j * (kIn / 4)) * 4;
    const float4 e = em4[tid];

    int hit = -1;
    if (e.x > 0.5f) hit = i0;
    if (e.y > 0.5f) hit = i0 + 1;
    if (e.z > 0.5f) hit = i0 + 2;
    if (e.w > 0.5f) hit = i0 + 3;

    if (hit >= 0) {
        const float iv = 1.0f / __ldg(vars_ + j);
        float4 p;
        p.x = __ldg(means + j);
        p.y = -0.72134752044448170f * iv * iv;   // -0.5 * log2(e) * inv_var^2
        p.z = __ldg(coefs + j);
        p.w = __int_as_float(hit);
        d_params[j] = p;
    }
}

// Main kernel. CTA = 256 threads; each thread owns 4 consecutive j and walks
// kRows consecutive batch rows. Per output: FADD, FMUL, FMUL, MUFU.EX2, FMUL.
// __stcs (evict-first) stores: in the steady-state graph-replay loop the 128MB
// output stream must NOT evict the small L2-resident read set (x, em, params) —
// timed A/B across rounds showed stcs is ~6us faster than evict-normal.
__global__ __launch_bounds__(256) void urbf_main(const float* __restrict__ x,
                                                 float* __restrict__ out) {
    using namespace urbf;
    const int jb = blockIdx.x & 3;
    const int rb = blockIdx.x >> 2;
    const int j = jb * kJBlk + threadIdx.x * 4;

    const float4 p0 = d_params[j];
    const float4 p1 = d_params[j + 1];
    const float4 p2 = d_params[j + 2];
    const float4 p3 = d_params[j + 3];
    const int s0 = __float_as_int(p0.w);
    const int s1 = __float_as_int(p1.w);
    const int s2 = __float_as_int(p2.w);
    const int s3 = __float_as_int(p3.w);
    const bool same_src = (s0 == s1) & (s1 == s2) & (s2 == s3);

    const float* xr = x + (size_t)rb * kRows * kIn;
    float* op = out + (size_t)rb * kRows * kOut + j;

    #pragma unroll
    for (int r = 0; r < kRows; ++r, xr += kIn, op += kOut) {
        float v0, v1, v2, v3;
        if (same_src) {
            v0 = __ldg(xr + s0);
            v1 = v0; v2 = v0; v3 = v0;
        } else {
            v0 = __ldg(xr + s0);
            v1 = __ldg(xr + s1);
            v2 = __ldg(xr + s2);
            v3 = __ldg(xr + s3);
        }

        const float t0 = v0 - p0.x;
        const float t1 = v1 - p1.x;
        const float t2 = v2 - p2.x;
        const float t3 = v3 - p3.x;

        float4 o;
        o.x = ex2_approx(p0.y * (t0 * t0)) * p0.z;
        o.y = ex2_approx(p1.y * (t1 * t1)) * p1.z;
        o.z = ex2_approx(p2.y * (t2 * t2)) * p2.z;
        o.w = ex2_approx(p3.y * (t3 * t3)) * p3.z;

        __stcs(reinterpret_cast<float4*>(op), o);
    }
}

extern "C" void kernel_launch(void* const* d_in, const int* in_sizes, int n_in,
                              void* d_out, int out_size) {
    using namespace urbf;
    const float* x     = (const float*)d_in[0];  // [8192, 256]
    const float* em    = (const float*)d_in[1];  // [4096, 256]
    const float* means = (const float*)d_in[2];  // [4096]
    const float* vars_ = (const float*)d_in[3];  // [4096]
    const float* coefs = (const float*)d_in[4];  // [4096]
    float* out = (float*)d_out;                  // [8192, 4096]

    {
        const int n4 = kOut * kIn / 4;                       // 262,144
        urbf_build_params<<<n4 / 256, 256>>>((const float4*)em, means, vars_, coefs);
    }
    {
        const int grid = (kOut / kJBlk) * (kBatch / kRows);  // 4096
        urbf_main<<<grid, 256>>>(x, out);
    }
}

// round 17
// speedup vs baseline: 1.4368x; 1.0504x over previous
#include <cuda_runtime.h>
#include <cuda_bf16.h>

// AdaptiveURBFLayer: out[b,j] = exp(-0.5*z^2)*coef[j], z = (x[b,src[j]]-mean[j])*inv_var[j]

namespace urbf {

constexpr int kIn    = 256;
constexpr int kOut   = 4096;
constexpr int kBatch = 8192;
constexpr int kRows  = 8;      // batch rows per CTA
constexpr int kJBlk  = 1024;   // j-span per CTA (256 threads x 4)

// Packed per-out-feature params: {mean, inv_var, coef, src_bits}
__device__ float4 d_params[kOut];

} // namespace urbf

// Prologue: scan expansion_mapping as float4 (one thread per vec4 element).
__global__ void urbf_build_params(const float4* __restrict__ em4,
                                  const float* __restrict__ means,
                                  const float* __restrict__ vars_,
                                  const float* __restrict__ coefs) {
    using namespace urbf;
    const int tid = blockIdx.x * blockDim.x + threadIdx.x;   // [0, kOut*kIn/4)
    const int j = tid / (kIn / 4);
    const int i0 = (tid - j * (kIn / 4)) * 4;
    const float4 e = em4[tid];

    int hit = -1;
    if (e.x > 0.5f) hit = i0;
    if (e.y > 0.5f) hit = i0 + 1;
    if (e.z > 0.5f) hit = i0 + 2;
    if (e.w > 0.5f) hit = i0 + 3;

    if (hit >= 0) {
        float4 p;
        p.x = __ldg(means + j);
        p.y = 1.0f / __ldg(vars_ + j);
        p.z = __ldg(coefs + j);
        p.w = __int_as_float(hit);
        d_params[j] = p;
    }
}

// Main kernel: 256 threads/CTA, 4 consecutive j per thread, 8 batch rows.
// __stcs stores (timed A/B winner: protects L2-resident reads from the 128MB
// output stream across graph replays). Uniform-src fast path front-batches
// all 8 gather LDGs (MLP=8) before the compute+store drain.
__global__ __launch_bounds__(256) void urbf_main(const float* __restrict__ x,
                                                 float* __restrict__ out) {
    using namespace urbf;
    const int jb = blockIdx.x & 3;
    const int rb = blockIdx.x >> 2;
    const int j = jb * kJBlk + threadIdx.x * 4;

    const float4 p0 = d_params[j];
    const float4 p1 = d_params[j + 1];
    const float4 p2 = d_params[j + 2];
    const float4 p3 = d_params[j + 3];
    const int s0 = __float_as_int(p0.w);
    const int s1 = __float_as_int(p1.w);
    const int s2 = __float_as_int(p2.w);
    const int s3 = __float_as_int(p3.w);
    const bool same_src = (s0 == s1) & (s1 == s2) & (s2 == s3);

    const float* xr = x + (size_t)rb * kRows * kIn;
    float* op = out + (size_t)rb * kRows * kOut + j;

    if (same_src) {
        // Front-batch the 8 gathers: all loads in flight before compute/stores.
        float v[kRows];
        #pragma unroll
        for (int r = 0; r < kRows; ++r)
            v[r] = __ldg(xr + r * kIn + s0);

        #pragma unroll
        for (int r = 0; r < kRows; ++r) {
            const float z0 = (v[r] - p0.x) * p0.y;
            const float z1 = (v[r] - p1.x) * p1.y;
            const float z2 = (v[r] - p2.x) * p2.y;
            const float z3 = (v[r] - p3.x) * p3.y;
            float4 o;
            o.x = __expf(-0.5f * z0 * z0) * p0.z;
            o.y = __expf(-0.5f * z1 * z1) * p1.z;
            o.z = __expf(-0.5f * z2 * z2) * p2.z;
            o.w = __expf(-0.5f * z3 * z3) * p3.z;
            __stcs(reinterpret_cast<float4*>(op + (size_t)r * kOut), o);
        }
    } else {
        // Generic one-hot mapping fallback (correct for any expansion matrix).
        #pragma unroll
        for (int r = 0; r < kRows; ++r) {
            const float* xp = xr + r * kIn;
            const float v0 = __ldg(xp + s0);
            const float v1 = __ldg(xp + s1);
            const float v2 = __ldg(xp + s2);
            const float v3 = __ldg(xp + s3);
            const float z0 = (v0 - p0.x) * p0.y;
            const float z1 = (v1 - p1.x) * p1.y;
            const float z2 = (v2 - p2.x) * p2.y;
            const float z3 = (v3 - p3.x) * p3.y;
            float4 o;
            o.x = __expf(-0.5f * z0 * z0) * p0.z;
            o.y = __expf(-0.5f * z1 * z1) * p1.z;
            o.z = __expf(-0.5f * z2 * z2) * p2.z;
            o.w = __expf(-0.5f * z3 * z3) * p3.z;
            __stcs(reinterpret_cast<float4*>(op + (size_t)r * kOut), o);
        }
    }
}

extern "C" void kernel_launch(void* const* d_in, const int* in_sizes, int n_in,
                              void* d_out, int out_size) {
    using namespace urbf;
    const float* x     = (const float*)d_in[0];  // [8192, 256]
    const float* em    = (const float*)d_in[1];  // [4096, 256]
    const float* means = (const float*)d_in[2];  // [4096]
    const float* vars_ = (const float*)d_in[3];  // [4096]
    const float* coefs = (const float*)d_in[4];  // [4096]
    float* out = (float*)d_out;                  // [8192, 4096]

    {
        const int n4 = kOut * kIn / 4;                       // 262,144
        urbf_build_params<<<n4 / 256, 256>>>((const float4*)em, means, vars_, coefs);
    }
    {
        const int grid = (kOut / kJBlk) * (kBatch / kRows);  // 4096
        urbf_main<<<grid, 256>>>(x, out);
    }
}